// round 9
// baseline (speedup 1.0000x reference)
#include <cuda_runtime.h>
#include <cuda_fp16.h>
#include <math.h>
#include <stdint.h>

// Problem constants
#define B_  4
#define L_  4096
#define E_  512
#define H_  16
#define ML  (B_*L_)            // 16384 tokens
#define EPS_ 1e-6f

// ---------------------------------------------------------------------------
// Scratch (static __device__ arrays; no allocation anywhere)
// ---------------------------------------------------------------------------
__device__ float g_Q[ML*E_];   // elu(q)+1
__device__ float g_K[ML*E_];   // elu(k)+1
__device__ float g_V[ML*E_];   // v projection (unscaled; /L * L cancels exactly)
__device__ float g_M[ML*E_];   // message

#define NCHUNK 32
#define KV_ELEMS   (B_*H_*32*32)     // 65536
#define KSUM_ELEMS (B_*H_*32)        // 2048
#define PART_STRIDE (KV_ELEMS + KSUM_ELEMS)   // 67584
__device__ float g_part[NCHUNK * PART_STRIDE];
__device__ float g_KV[KV_ELEMS];
__device__ float g_Ksum[KSUM_ELEMS];

// ---------------------------------------------------------------------------
// PTX helpers: ldmatrix + fp16 mma (fp32 accumulate)
// ---------------------------------------------------------------------------
__device__ __forceinline__ unsigned smem_u32(const void* p) {
    return (unsigned)__cvta_generic_to_shared(p);
}
__device__ __forceinline__ void ldsm_x4(unsigned* r, unsigned addr) {
    asm volatile("ldmatrix.sync.aligned.m8n8.x4.shared.b16 {%0,%1,%2,%3}, [%4];"
                 : "=r"(r[0]), "=r"(r[1]), "=r"(r[2]), "=r"(r[3]) : "r"(addr));
}
__device__ __forceinline__ void mma_f16(float* c, const unsigned* a, const unsigned* b) {
    asm volatile("mma.sync.aligned.m16n8k16.row.col.f32.f16.f16.f32 "
                 "{%0,%1,%2,%3}, {%4,%5,%6,%7}, {%8,%9}, {%0,%1,%2,%3};"
                 : "+f"(c[0]), "+f"(c[1]), "+f"(c[2]), "+f"(c[3])
                 : "r"(a[0]), "r"(a[1]), "r"(a[2]), "r"(a[3]),
                   "r"(b[0]), "r"(b[1]));
}

// ---------------------------------------------------------------------------
// 8 fp32 -> fp16 hi (rn) + fp16 lo (exact residual, rn): ~22 mantissa bits
// ---------------------------------------------------------------------------
__device__ __forceinline__ void cvt8_split(const float* __restrict__ v8,
                                           uint4& h, uint4& l) {
    uint32_t hp[4], lp[4];
    #pragma unroll
    for (int i = 0; i < 4; i++) {
        float x0 = v8[2*i], x1 = v8[2*i+1];
        __half2 hh = __floats2half2_rn(x0, x1);
        float2 hf = __half22float2(hh);
        __half2 ll = __floats2half2_rn(x0 - hf.x, x1 - hf.y);
        hp[i] = *(uint32_t*)&hh;
        lp[i] = *(uint32_t*)&ll;
    }
    h = make_uint4(hp[0], hp[1], hp[2], hp[3]);
    l = make_uint4(lp[0], lp[1], lp[2], lp[3]);
}
// 8 fp32 -> single fp16 (rn); ~2^-12 relative (the error budget term)
__device__ __forceinline__ void cvt8_h(const float* __restrict__ v8, uint4& h) {
    uint32_t hp[4];
    #pragma unroll
    for (int i = 0; i < 4; i++) {
        __half2 hh = __floats2half2_rn(v8[2*i], v8[2*i+1]);
        hp[i] = *(uint32_t*)&hh;
    }
    h = make_uint4(hp[0], hp[1], hp[2], hp[3]);
}

// ---------------------------------------------------------------------------
// GEMM: C[M,N] = A[M,K] @ W[N,K]^T, fp32 in/out, fp16x2 split internally.
//   C = Ahi*W + Alo*W     (A to ~22 bits; W single fp16 ~2^-12 rel err)
// Block 128x128, k-tile 32, 8 warps, warp tile 32x64, mma.m16n8k16,
// smem row stride 40 halves (conflict-free ldmatrix).
// DOUBLE-BUFFERED staging: stores go to the other buffer, ONE barrier per
// k-tile, cvt+STS placed between the two ks-halves of the mma work so the
// store stream overlaps the tensor stream instead of serializing behind it.
// ---------------------------------------------------------------------------
#define TSZ   (128 * 40)                 // halves per operand per buffer
#define BUFB  (3 * TSZ * 2)              // bytes per buffer (Ah|Al|B) = 30720
#define GSMEM (2 * BUFB)                 // 61440 B dynamic smem

struct GemmArgs {
    const float* A[3]; const float* W[3]; float* C[3];
    int actmask;
};

__global__ __launch_bounds__(256)
void gemm_f16x2(GemmArgs args)
{
    extern __shared__ char smem[];
    const int z = blockIdx.z;
    const float* A = args.A[z];
    const float* W = args.W[z];
    float*       C = args.C[z];
    const bool act = (args.actmask >> z) & 1;

    const int tid  = threadIdx.x;
    const int lane = tid & 31;
    const int warp = tid >> 5;
    const int m0 = blockIdx.y * 128;
    const int n0 = blockIdx.x * 128;
    const int wm0 = (warp & 3) * 32;     // warp row origin in tile
    const int wn0 = (warp >> 2) * 64;    // warp col origin in tile

    // global-load mapping: each thread owns one 16-float row segment
    const int lrow = tid >> 1;           // 0..127
    const int lkc  = (tid & 1) * 16;     // k offset 0 or 16

    const float* gA = A + (size_t)(m0 + lrow) * 512 + lkc;
    const float* gB = W + (size_t)(n0 + lrow) * 512 + lkc;

    float acc[2][8][4];
    #pragma unroll
    for (int i = 0; i < 2; i++)
        #pragma unroll
        for (int j = 0; j < 8; j++)
            #pragma unroll
            for (int t = 0; t < 4; t++) acc[i][j][t] = 0.0f;

    const int sOfs = lrow * 40 + lkc;    // element offset within an operand

    // store regs->smem buffer (cvt fused)
    auto store_tile = [&](char* base, const float4* ra, const float4* rb) {
        __half* bAh = (__half*)(base);
        __half* bAl = (__half*)(base + TSZ * 2);
        __half* bB  = (__half*)(base + 2 * TSZ * 2);
        uint4 h0, l0, h1, l1;
        cvt8_split((const float*)&ra[0], h0, l0);
        cvt8_split((const float*)&ra[2], h1, l1);
        *(uint4*)&bAh[sOfs] = h0; *(uint4*)&bAh[sOfs + 8] = h1;
        *(uint4*)&bAl[sOfs] = l0; *(uint4*)&bAl[sOfs + 8] = l1;
        cvt8_h((const float*)&rb[0], h0);
        cvt8_h((const float*)&rb[2], h1);
        *(uint4*)&bB[sOfs] = h0; *(uint4*)&bB[sOfs + 8] = h1;
    };

    // ---- prologue: tile 0 -> buf 0 ----
    float4 ra[4], rb[4];
    #pragma unroll
    for (int i = 0; i < 4; i++) {
        ra[i] = *(const float4*)(gA + 4 * i);
        rb[i] = *(const float4*)(gB + 4 * i);
    }
    store_tile(smem, ra, rb);
    __syncthreads();

    // ldmatrix address components
    const int a_r = lane & 15;              // row within m16 tile
    const int a_c = (lane >> 4) * 8;        // col half
    const int b_r = lane & 7;               // row within n8 tile
    const int b_nt = (lane >> 4) & 1;       // which of 2 n-tiles in x4
    const int b_c = ((lane >> 3) & 1) * 8;  // col half

    // one ks-halve of mma work on a given buffer
    auto mma_half = [&](char* base, int kk) {
        __half* bAh = (__half*)(base);
        __half* bAl = (__half*)(base + TSZ * 2);
        __half* bB  = (__half*)(base + 2 * TSZ * 2);
        unsigned ah[2][4], al[2][4];
        ldsm_x4(ah[0], smem_u32(&bAh[(wm0 + a_r) * 40 + kk + a_c]));
        ldsm_x4(ah[1], smem_u32(&bAh[(wm0 + 16 + a_r) * 40 + kk + a_c]));
        ldsm_x4(al[0], smem_u32(&bAl[(wm0 + a_r) * 40 + kk + a_c]));
        ldsm_x4(al[1], smem_u32(&bAl[(wm0 + 16 + a_r) * 40 + kk + a_c]));
        #pragma unroll
        for (int ntp = 0; ntp < 4; ntp++) {
            unsigned b[4];
            const int brow = wn0 + ntp * 16 + b_nt * 8 + b_r;
            ldsm_x4(b, smem_u32(&bB[brow * 40 + kk + b_c]));
            #pragma unroll
            for (int half = 0; half < 2; half++) {
                const int nt = ntp * 2 + half;
                const unsigned* bp = b + 2 * half;
                mma_f16(acc[0][nt], ah[0], bp);
                mma_f16(acc[0][nt], al[0], bp);
                mma_f16(acc[1][nt], ah[1], bp);
                mma_f16(acc[1][nt], al[1], bp);
            }
        }
    };

    for (int kt = 0; kt < 16; ++kt) {
        char* cur = smem + (kt & 1) * BUFB;
        char* nxt = smem + ((kt + 1) & 1) * BUFB;

        if (kt < 15) {
            const int ko = (kt + 1) * 32;
            #pragma unroll
            for (int i = 0; i < 4; i++) {
                ra[i] = *(const float4*)(gA + ko + 4 * i);
                rb[i] = *(const float4*)(gB + ko + 4 * i);
            }
        }

        mma_half(cur, 0);                 // covers global-load latency
        if (kt < 15) store_tile(nxt, ra, rb);   // other buffer: no barrier needed
        mma_half(cur, 16);                // covers store drain
        if (kt < 15) __syncthreads();     // single barrier per k-tile
    }

    // ---- epilogue: optional elu(x)+1 (= x+1 if x>0 else exp(x)), fp32 out ----
    const int row0 = m0 + wm0 + (lane >> 2);
    const int col0 = n0 + wn0 + (lane & 3) * 2;
    #pragma unroll
    for (int mt = 0; mt < 2; mt++) {
        #pragma unroll
        for (int nt = 0; nt < 8; nt++) {
            float c0 = acc[mt][nt][0], c1 = acc[mt][nt][1];
            float c2 = acc[mt][nt][2], c3 = acc[mt][nt][3];
            if (act) {
                c0 = (c0 > 0.0f) ? (c0 + 1.0f) : expf(c0);
                c1 = (c1 > 0.0f) ? (c1 + 1.0f) : expf(c1);
                c2 = (c2 > 0.0f) ? (c2 + 1.0f) : expf(c2);
                c3 = (c3 > 0.0f) ? (c3 + 1.0f) : expf(c3);
            }
            const int r = row0 + mt * 16;
            const int cc = col0 + nt * 8;
            *(float2*)(C + (size_t)r * 512 + cc)       = make_float2(c0, c1);
            *(float2*)(C + (size_t)(r + 8) * 512 + cc) = make_float2(c2, c3);
        }
    }
}

// ---------------------------------------------------------------------------
// Stage 2a: per-(s-chunk, b, h) partial KV[d][dv] = sum_s K[s,d]*V[s,dv]
// and partial Ksum[d]. Deterministic (no float atomics). NCHUNK=32.
// ---------------------------------------------------------------------------
__global__ void kv_partial(const float* __restrict__ Kf,
                           const float* __restrict__ Vf,
                           float* __restrict__ part)
{
    const int c  = blockIdx.x;
    const int bh = blockIdx.y;
    const int b  = bh >> 4;
    const int h  = bh & 15;
    const int tid = threadIdx.x;

    __shared__ __align__(16) float Ks[8][32];
    __shared__ __align__(16) float Vs[8][32];

    const int d   = tid >> 3;
    const int dv0 = (tid & 7) << 2;
    const int lr  = tid >> 5;   // 0..7
    const int lc  = tid & 31;

    const size_t base = ((size_t)(b * L_ + c * (L_ / NCHUNK)) * 512) + h * 32;
    const float* Kb = Kf + base;
    const float* Vb = Vf + base;

    float a0 = 0.f, a1 = 0.f, a2 = 0.f, a3 = 0.f, ks = 0.f;

    for (int s = 0; s < L_ / NCHUNK; s += 8) {
        Ks[lr][lc] = Kb[(size_t)(s + lr) * 512 + lc];
        Vs[lr][lc] = Vb[(size_t)(s + lr) * 512 + lc];
        __syncthreads();
        #pragma unroll
        for (int u = 0; u < 8; u++) {
            float kd = Ks[u][d];
            float4 vv = *(const float4*)&Vs[u][dv0];
            a0 += kd * vv.x; a1 += kd * vv.y;
            a2 += kd * vv.z; a3 += kd * vv.w;
            ks += kd;
        }
        __syncthreads();
    }

    float* p = part + (size_t)c * PART_STRIDE;
    const int o = bh * 1024 + d * 32 + dv0;
    p[o + 0] = a0; p[o + 1] = a1; p[o + 2] = a2; p[o + 3] = a3;
    if ((tid & 7) == 0) p[KV_ELEMS + bh * 32 + d] = ks;
}

// Stage 2b: reduce NCHUNK partials -> g_KV, g_Ksum (deterministic order)
__global__ void kv_reduce(const float* __restrict__ part,
                          float* __restrict__ KV,
                          float* __restrict__ Ksum)
{
    const int i = blockIdx.x * 256 + threadIdx.x;
    if (i >= PART_STRIDE) return;
    float s = 0.f;
    #pragma unroll
    for (int c = 0; c < NCHUNK; c++) s += part[(size_t)c * PART_STRIDE + i];
    if (i < KV_ELEMS) KV[i] = s;
    else              Ksum[i - KV_ELEMS] = s;
}

// ---------------------------------------------------------------------------
// Stage 3: message. One thread per (token, head): its 32-float row load and
// store are a full 128B line per lane (perfect sectors, no smem staging).
// Only KV (broadcast) + Ksum stay in smem -> high occupancy.
// Z = 1/(Q.Ksum + eps); msg[dv] = Z * sum_d Q[d]*KV[d][dv]
// ---------------------------------------------------------------------------
__global__ __launch_bounds__(256)
void msg_kernel(const float* __restrict__ Qf,
                const float* __restrict__ KV,
                const float* __restrict__ Ksum,
                float* __restrict__ Msg)
{
    const int h  = blockIdx.y;
    const int b  = blockIdx.z;
    const int bh = b * 16 + h;
    const int tid = threadIdx.x;
    const int l  = blockIdx.x * 256 + tid;

    __shared__ __align__(16) float KVs[1024];
    __shared__ float ks[32];

    for (int i = tid; i < 1024; i += 256) KVs[i] = KV[(size_t)bh * 1024 + i];
    if (tid < 32) ks[tid] = Ksum[bh * 32 + tid];
    __syncthreads();

    const float* Qb = Qf + ((size_t)(b * L_ + l) * 512) + h * 32;
    float qr[32];
    #pragma unroll
    for (int i = 0; i < 8; i++) {
        float4 q4 = *(const float4*)(Qb + 4 * i);
        qr[4*i+0] = q4.x; qr[4*i+1] = q4.y; qr[4*i+2] = q4.z; qr[4*i+3] = q4.w;
    }

    float zden = 0.f;
    #pragma unroll
    for (int d = 0; d < 32; d++) zden += qr[d] * ks[d];
    const float z = 1.0f / (zden + EPS_);

    float* Mb = Msg + ((size_t)(b * L_ + l) * 512) + h * 32;
    const float4* KV4 = (const float4*)KVs;
    #pragma unroll
    for (int dq = 0; dq < 8; dq++) {
        float mx = 0.f, my = 0.f, mz = 0.f, mw = 0.f;
        #pragma unroll
        for (int d = 0; d < 32; d++) {
            float4 kv = KV4[d * 8 + dq];       // warp-broadcast LDS
            mx += qr[d] * kv.x; my += qr[d] * kv.y;
            mz += qr[d] * kv.z; mw += qr[d] * kv.w;
        }
        *(float4*)(Mb + dq * 4) = make_float4(mx * z, my * z, mz * z, mw * z);
    }
}

// ---------------------------------------------------------------------------
// Launch. Inputs (metadata order): query, key, value, Wq, Wk, Wv, Wm. f32 out.
// ---------------------------------------------------------------------------
extern "C" void kernel_launch(void* const* d_in, const int* in_sizes, int n_in,
                              void* d_out, int out_size)
{
    (void)in_sizes; (void)n_in; (void)out_size;
    const float* q  = (const float*)d_in[0];
    const float* k  = (const float*)d_in[1];
    const float* v  = (const float*)d_in[2];
    const float* Wq = (const float*)d_in[3];
    const float* Wk = (const float*)d_in[4];
    const float* Wv = (const float*)d_in[5];
    const float* Wm = (const float*)d_in[6];
    float* out = (float*)d_out;

    float *gQ, *gK, *gV, *gM, *gPart, *gKV, *gKs;
    cudaGetSymbolAddress((void**)&gQ,    g_Q);
    cudaGetSymbolAddress((void**)&gK,    g_K);
    cudaGetSymbolAddress((void**)&gV,    g_V);
    cudaGetSymbolAddress((void**)&gM,    g_M);
    cudaGetSymbolAddress((void**)&gPart, g_part);
    cudaGetSymbolAddress((void**)&gKV,   g_KV);
    cudaGetSymbolAddress((void**)&gKs,   g_Ksum);

    cudaFuncSetAttribute(gemm_f16x2, cudaFuncAttributeMaxDynamicSharedMemorySize,
                         GSMEM);

    // 1) fused projections (fp16x2 split in staging): q,k -> elu+1 ; v -> raw
    {
        GemmArgs a;
        a.A[0] = q; a.W[0] = Wq; a.C[0] = gQ;
        a.A[1] = k; a.W[1] = Wk; a.C[1] = gK;
        a.A[2] = v; a.W[2] = Wv; a.C[2] = gV;
        a.actmask = 0x3;
        gemm_f16x2<<<dim3(4, 128, 3), 256, GSMEM>>>(a);
    }

    // 2) KV + Ksum (deterministic two-phase reduction)
    kv_partial<<<dim3(NCHUNK, B_ * H_), 256>>>(gK, gV, gPart);
    kv_reduce<<<(PART_STRIDE + 255) / 256, 256>>>(gPart, gKV, gKs);

    // 3) message
    msg_kernel<<<dim3(L_ / 256, H_, B_), 256>>>(gQ, gKV, gKs, gM);

    // 4) output merge projection
    {
        GemmArgs a;
        a.A[0] = gM; a.W[0] = Wm; a.C[0] = out;
        a.A[1] = gM; a.W[1] = Wm; a.C[1] = out;
        a.A[2] = gM; a.W[2] = Wm; a.C[2] = out;
        a.actmask = 0;
        gemm_f16x2<<<dim3(4, 128, 1), 256, GSMEM>>>(a);
    }
}

// round 10
// speedup vs baseline: 1.1854x; 1.1854x over previous
#include <cuda_runtime.h>
#include <cuda_fp16.h>
#include <math.h>
#include <stdint.h>

// Problem constants
#define B_  4
#define L_  4096
#define E_  512
#define H_  16
#define ML  (B_*L_)            // 16384 tokens
#define EPS_ 1e-6f

// ---------------------------------------------------------------------------
// Scratch (static __device__ arrays; no allocation anywhere)
// ---------------------------------------------------------------------------
__device__ float g_Q[ML*E_];   // elu(q)+1
__device__ float g_K[ML*E_];   // elu(k)+1
__device__ float g_V[ML*E_];   // v projection (unscaled; /L * L cancels exactly)
__device__ float g_M[ML*E_];   // message

#define NCHUNK 32
#define KV_ELEMS   (B_*H_*32*32)     // 65536
#define KSUM_ELEMS (B_*H_*32)        // 2048
#define PART_STRIDE (KV_ELEMS + KSUM_ELEMS)   // 67584
__device__ float g_part[NCHUNK * PART_STRIDE];
__device__ float g_KV[KV_ELEMS];
__device__ float g_Ksum[KSUM_ELEMS];

// ---------------------------------------------------------------------------
// PTX helpers: ldmatrix + fp16 mma (fp32 accumulate)
// ---------------------------------------------------------------------------
__device__ __forceinline__ unsigned smem_u32(const void* p) {
    return (unsigned)__cvta_generic_to_shared(p);
}
__device__ __forceinline__ void ldsm_x4(unsigned* r, unsigned addr) {
    asm volatile("ldmatrix.sync.aligned.m8n8.x4.shared.b16 {%0,%1,%2,%3}, [%4];"
                 : "=r"(r[0]), "=r"(r[1]), "=r"(r[2]), "=r"(r[3]) : "r"(addr));
}
__device__ __forceinline__ void mma_f16(float* c, const unsigned* a, const unsigned* b) {
    asm volatile("mma.sync.aligned.m16n8k16.row.col.f32.f16.f16.f32 "
                 "{%0,%1,%2,%3}, {%4,%5,%6,%7}, {%8,%9}, {%0,%1,%2,%3};"
                 : "+f"(c[0]), "+f"(c[1]), "+f"(c[2]), "+f"(c[3])
                 : "r"(a[0]), "r"(a[1]), "r"(a[2]), "r"(a[3]),
                   "r"(b[0]), "r"(b[1]));
}

// ---------------------------------------------------------------------------
// 8 fp32 -> fp16 hi (rn) + fp16 lo (exact residual, rn): ~22 mantissa bits
// ---------------------------------------------------------------------------
__device__ __forceinline__ void cvt8_split(const float* __restrict__ v8,
                                           uint4& h, uint4& l) {
    uint32_t hp[4], lp[4];
    #pragma unroll
    for (int i = 0; i < 4; i++) {
        float x0 = v8[2*i], x1 = v8[2*i+1];
        __half2 hh = __floats2half2_rn(x0, x1);
        float2 hf = __half22float2(hh);
        __half2 ll = __floats2half2_rn(x0 - hf.x, x1 - hf.y);
        hp[i] = *(uint32_t*)&hh;
        lp[i] = *(uint32_t*)&ll;
    }
    h = make_uint4(hp[0], hp[1], hp[2], hp[3]);
    l = make_uint4(lp[0], lp[1], lp[2], lp[3]);
}
// 8 fp32 -> single fp16 (rn); ~2^-12 relative (the error budget term)
__device__ __forceinline__ void cvt8_h(const float* __restrict__ v8, uint4& h) {
    uint32_t hp[4];
    #pragma unroll
    for (int i = 0; i < 4; i++) {
        __half2 hh = __floats2half2_rn(v8[2*i], v8[2*i+1]);
        hp[i] = *(uint32_t*)&hh;
    }
    h = make_uint4(hp[0], hp[1], hp[2], hp[3]);
}

// ---------------------------------------------------------------------------
// GEMM: C[M,N] = A[M,K] @ W[N,K]^T, fp32 in/out, fp16x2 split internally.
//   C = Ahi*W + Alo*W     (A to ~22 bits; W single fp16 ~2^-12 rel err)
// Block 128x128, k-tile 32, 8 warps, warp tile 32x64, mma.m16n8k16,
// smem row stride 40 halves (conflict-free ldmatrix), register prefetch.
// (R8 schedule restored: single buffer, two barriers — measured best.)
// __launch_bounds__(256, 2) caps regs at 128 -> guarantees 2 CTAs/SM.
// ---------------------------------------------------------------------------
struct GemmArgs {
    const float* A[3]; const float* W[3]; float* C[3];
    int actmask;
};

__global__ __launch_bounds__(256, 2)
void gemm_f16x2(GemmArgs args)
{
    const int z = blockIdx.z;
    const float* A = args.A[z];
    const float* W = args.W[z];
    float*       C = args.C[z];
    const bool act = (args.actmask >> z) & 1;

    __shared__ __half sAh[128 * 40];
    __shared__ __half sAl[128 * 40];
    __shared__ __half sB [128 * 40];

    const int tid  = threadIdx.x;
    const int lane = tid & 31;
    const int warp = tid >> 5;
    const int m0 = blockIdx.y * 128;
    const int n0 = blockIdx.x * 128;
    const int wm0 = (warp & 3) * 32;     // warp row origin in tile
    const int wn0 = (warp >> 2) * 64;    // warp col origin in tile

    // global-load mapping: each thread owns one 16-float row segment
    const int lrow = tid >> 1;           // 0..127
    const int lkc  = (tid & 1) * 16;     // k offset 0 or 16

    const float* gA = A + (size_t)(m0 + lrow) * 512 + lkc;
    const float* gB = W + (size_t)(n0 + lrow) * 512 + lkc;

    float acc[2][8][4];
    #pragma unroll
    for (int i = 0; i < 2; i++)
        #pragma unroll
        for (int j = 0; j < 8; j++)
            #pragma unroll
            for (int t = 0; t < 4; t++) acc[i][j][t] = 0.0f;

    const int sA0 = lrow * 40 + lkc;

    // ---- prologue: load k-tile 0 (fp32) ----
    float4 ra[4], rb[4];
    #pragma unroll
    for (int i = 0; i < 4; i++) {
        ra[i] = *(const float4*)(gA + 4 * i);
        rb[i] = *(const float4*)(gB + 4 * i);
    }
    {
        uint4 h0, l0, h1, l1;
        cvt8_split((const float*)&ra[0], h0, l0);
        cvt8_split((const float*)&ra[2], h1, l1);
        *(uint4*)&sAh[sA0] = h0; *(uint4*)&sAh[sA0 + 8] = h1;
        *(uint4*)&sAl[sA0] = l0; *(uint4*)&sAl[sA0 + 8] = l1;
        cvt8_h((const float*)&rb[0], h0);
        cvt8_h((const float*)&rb[2], h1);
        *(uint4*)&sB[sA0] = h0; *(uint4*)&sB[sA0 + 8] = h1;
    }
    __syncthreads();

    // ldmatrix address components
    const int a_r = lane & 15;              // row within m16 tile
    const int a_c = (lane >> 4) * 8;        // col half
    const int b_r = lane & 7;               // row within n8 tile
    const int b_nt = (lane >> 4) & 1;       // which of 2 n-tiles in x4
    const int b_c = ((lane >> 3) & 1) * 8;  // col half

    for (int kt = 0; kt < 16; ++kt) {
        if (kt < 15) {
            const int ko = (kt + 1) * 32;
            #pragma unroll
            for (int i = 0; i < 4; i++) {
                ra[i] = *(const float4*)(gA + ko + 4 * i);
                rb[i] = *(const float4*)(gB + ko + 4 * i);
            }
        }

        #pragma unroll
        for (int ks = 0; ks < 2; ks++) {
            const int kk = ks * 16;
            unsigned ah[2][4], al[2][4];
            ldsm_x4(ah[0], smem_u32(&sAh[(wm0 + a_r) * 40 + kk + a_c]));
            ldsm_x4(ah[1], smem_u32(&sAh[(wm0 + 16 + a_r) * 40 + kk + a_c]));
            ldsm_x4(al[0], smem_u32(&sAl[(wm0 + a_r) * 40 + kk + a_c]));
            ldsm_x4(al[1], smem_u32(&sAl[(wm0 + 16 + a_r) * 40 + kk + a_c]));

            #pragma unroll
            for (int ntp = 0; ntp < 4; ntp++) {
                unsigned b[4];
                const int brow = wn0 + ntp * 16 + b_nt * 8 + b_r;
                ldsm_x4(b, smem_u32(&sB[brow * 40 + kk + b_c]));
                #pragma unroll
                for (int half = 0; half < 2; half++) {
                    const int nt = ntp * 2 + half;
                    const unsigned* bp = b + 2 * half;
                    mma_f16(acc[0][nt], ah[0], bp);
                    mma_f16(acc[0][nt], al[0], bp);
                    mma_f16(acc[1][nt], ah[1], bp);
                    mma_f16(acc[1][nt], al[1], bp);
                }
            }
        }

        if (kt < 15) {
            __syncthreads();
            uint4 h0, l0, h1, l1;
            cvt8_split((const float*)&ra[0], h0, l0);
            cvt8_split((const float*)&ra[2], h1, l1);
            *(uint4*)&sAh[sA0] = h0; *(uint4*)&sAh[sA0 + 8] = h1;
            *(uint4*)&sAl[sA0] = l0; *(uint4*)&sAl[sA0 + 8] = l1;
            cvt8_h((const float*)&rb[0], h0);
            cvt8_h((const float*)&rb[2], h1);
            *(uint4*)&sB[sA0] = h0; *(uint4*)&sB[sA0 + 8] = h1;
            __syncthreads();
        }
    }

    // ---- epilogue: optional elu(x)+1 (= x+1 if x>0 else exp(x)), fp32 out ----
    const int row0 = m0 + wm0 + (lane >> 2);
    const int col0 = n0 + wn0 + (lane & 3) * 2;
    #pragma unroll
    for (int mt = 0; mt < 2; mt++) {
        #pragma unroll
        for (int nt = 0; nt < 8; nt++) {
            float c0 = acc[mt][nt][0], c1 = acc[mt][nt][1];
            float c2 = acc[mt][nt][2], c3 = acc[mt][nt][3];
            if (act) {
                c0 = (c0 > 0.0f) ? (c0 + 1.0f) : expf(c0);
                c1 = (c1 > 0.0f) ? (c1 + 1.0f) : expf(c1);
                c2 = (c2 > 0.0f) ? (c2 + 1.0f) : expf(c2);
                c3 = (c3 > 0.0f) ? (c3 + 1.0f) : expf(c3);
            }
            const int r = row0 + mt * 16;
            const int cc = col0 + nt * 8;
            *(float2*)(C + (size_t)r * 512 + cc)       = make_float2(c0, c1);
            *(float2*)(C + (size_t)(r + 8) * 512 + cc) = make_float2(c2, c3);
        }
    }
}

// ---------------------------------------------------------------------------
// Stage 2a: per-(s-chunk, b, h) partial KV[d][dv] = sum_s K[s,d]*V[s,dv]
// and partial Ksum[d]. Deterministic (no float atomics). NCHUNK=32.
// ---------------------------------------------------------------------------
__global__ void kv_partial(const float* __restrict__ Kf,
                           const float* __restrict__ Vf,
                           float* __restrict__ part)
{
    const int c  = blockIdx.x;
    const int bh = blockIdx.y;
    const int b  = bh >> 4;
    const int h  = bh & 15;
    const int tid = threadIdx.x;

    __shared__ __align__(16) float Ks[8][32];
    __shared__ __align__(16) float Vs[8][32];

    const int d   = tid >> 3;
    const int dv0 = (tid & 7) << 2;
    const int lr  = tid >> 5;   // 0..7
    const int lc  = tid & 31;

    const size_t base = ((size_t)(b * L_ + c * (L_ / NCHUNK)) * 512) + h * 32;
    const float* Kb = Kf + base;
    const float* Vb = Vf + base;

    float a0 = 0.f, a1 = 0.f, a2 = 0.f, a3 = 0.f, ks = 0.f;

    for (int s = 0; s < L_ / NCHUNK; s += 8) {
        Ks[lr][lc] = Kb[(size_t)(s + lr) * 512 + lc];
        Vs[lr][lc] = Vb[(size_t)(s + lr) * 512 + lc];
        __syncthreads();
        #pragma unroll
        for (int u = 0; u < 8; u++) {
            float kd = Ks[u][d];
            float4 vv = *(const float4*)&Vs[u][dv0];
            a0 += kd * vv.x; a1 += kd * vv.y;
            a2 += kd * vv.z; a3 += kd * vv.w;
            ks += kd;
        }
        __syncthreads();
    }

    float* p = part + (size_t)c * PART_STRIDE;
    const int o = bh * 1024 + d * 32 + dv0;
    p[o + 0] = a0; p[o + 1] = a1; p[o + 2] = a2; p[o + 3] = a3;
    if ((tid & 7) == 0) p[KV_ELEMS + bh * 32 + d] = ks;
}

// Stage 2b: reduce NCHUNK partials -> g_KV, g_Ksum (deterministic order)
__global__ void kv_reduce(const float* __restrict__ part,
                          float* __restrict__ KV,
                          float* __restrict__ Ksum)
{
    const int i = blockIdx.x * 256 + threadIdx.x;
    if (i >= PART_STRIDE) return;
    float s = 0.f;
    #pragma unroll
    for (int c = 0; c < NCHUNK; c++) s += part[(size_t)c * PART_STRIDE + i];
    if (i < KV_ELEMS) KV[i] = s;
    else              Ksum[i - KV_ELEMS] = s;
}

// ---------------------------------------------------------------------------
// Stage 3: message. One thread per (token, head): its 32-float row load and
// store are a full 128B line per lane (perfect sectors, no smem staging).
// Only KV (broadcast) + Ksum stay in smem -> high occupancy.
// Z = 1/(Q.Ksum + eps); msg[dv] = Z * sum_d Q[d]*KV[d][dv]
// ---------------------------------------------------------------------------
__global__ __launch_bounds__(256)
void msg_kernel(const float* __restrict__ Qf,
                const float* __restrict__ KV,
                const float* __restrict__ Ksum,
                float* __restrict__ Msg)
{
    const int h  = blockIdx.y;
    const int b  = blockIdx.z;
    const int bh = b * 16 + h;
    const int tid = threadIdx.x;
    const int l  = blockIdx.x * 256 + tid;

    __shared__ __align__(16) float KVs[1024];
    __shared__ float ks[32];

    for (int i = tid; i < 1024; i += 256) KVs[i] = KV[(size_t)bh * 1024 + i];
    if (tid < 32) ks[tid] = Ksum[bh * 32 + tid];
    __syncthreads();

    const float* Qb = Qf + ((size_t)(b * L_ + l) * 512) + h * 32;
    float qr[32];
    #pragma unroll
    for (int i = 0; i < 8; i++) {
        float4 q4 = *(const float4*)(Qb + 4 * i);
        qr[4*i+0] = q4.x; qr[4*i+1] = q4.y; qr[4*i+2] = q4.z; qr[4*i+3] = q4.w;
    }

    float zden = 0.f;
    #pragma unroll
    for (int d = 0; d < 32; d++) zden += qr[d] * ks[d];
    const float z = 1.0f / (zden + EPS_);

    float* Mb = Msg + ((size_t)(b * L_ + l) * 512) + h * 32;
    const float4* KV4 = (const float4*)KVs;
    #pragma unroll
    for (int dq = 0; dq < 8; dq++) {
        float mx = 0.f, my = 0.f, mz = 0.f, mw = 0.f;
        #pragma unroll
        for (int d = 0; d < 32; d++) {
            float4 kv = KV4[d * 8 + dq];       // warp-broadcast LDS
            mx += qr[d] * kv.x; my += qr[d] * kv.y;
            mz += qr[d] * kv.z; mw += qr[d] * kv.w;
        }
        *(float4*)(Mb + dq * 4) = make_float4(mx * z, my * z, mz * z, mw * z);
    }
}

// ---------------------------------------------------------------------------
// Launch. Inputs (metadata order): query, key, value, Wq, Wk, Wv, Wm. f32 out.
// ---------------------------------------------------------------------------
extern "C" void kernel_launch(void* const* d_in, const int* in_sizes, int n_in,
                              void* d_out, int out_size)
{
    (void)in_sizes; (void)n_in; (void)out_size;
    const float* q  = (const float*)d_in[0];
    const float* k  = (const float*)d_in[1];
    const float* v  = (const float*)d_in[2];
    const float* Wq = (const float*)d_in[3];
    const float* Wk = (const float*)d_in[4];
    const float* Wv = (const float*)d_in[5];
    const float* Wm = (const float*)d_in[6];
    float* out = (float*)d_out;

    float *gQ, *gK, *gV, *gM, *gPart, *gKV, *gKs;
    cudaGetSymbolAddress((void**)&gQ,    g_Q);
    cudaGetSymbolAddress((void**)&gK,    g_K);
    cudaGetSymbolAddress((void**)&gV,    g_V);
    cudaGetSymbolAddress((void**)&gM,    g_M);
    cudaGetSymbolAddress((void**)&gPart, g_part);
    cudaGetSymbolAddress((void**)&gKV,   g_KV);
    cudaGetSymbolAddress((void**)&gKs,   g_Ksum);

    // 1) fused projections (fp16x2 split in staging): q,k -> elu+1 ; v -> raw
    {
        GemmArgs a;
        a.A[0] = q; a.W[0] = Wq; a.C[0] = gQ;
        a.A[1] = k; a.W[1] = Wk; a.C[1] = gK;
        a.A[2] = v; a.W[2] = Wv; a.C[2] = gV;
        a.actmask = 0x3;
        gemm_f16x2<<<dim3(4, 128, 3), 256>>>(a);
    }

    // 2) KV + Ksum (deterministic two-phase reduction)
    kv_partial<<<dim3(NCHUNK, B_ * H_), 256>>>(gK, gV, gPart);
    kv_reduce<<<(PART_STRIDE + 255) / 256, 256>>>(gPart, gKV, gKs);

    // 3) message
    msg_kernel<<<dim3(L_ / 256, H_, B_), 256>>>(gQ, gKV, gKs, gM);

    // 4) output merge projection
    {
        GemmArgs a;
        a.A[0] = gM; a.W[0] = Wm; a.C[0] = out;
        a.A[1] = gM; a.W[1] = Wm; a.C[1] = out;
        a.A[2] = gM; a.W[2] = Wm; a.C[2] = out;
        a.actmask = 0;
        gemm_f16x2<<<dim3(4, 128, 1), 256>>>(a);
    }
}